// round 4
// baseline (speedup 1.0000x reference)
#include <cuda_runtime.h>
#include <cuda_bf16.h>
#include <math.h>

// Problem constants (from reference setup_inputs)
#define B_   32
#define IDF_ 128
#define CDF_ 256
#define IH_  128
#define IW_  128
#define QL_  (IH_ * IW_)   // 16384
#define SL_  24
#define SLP_ (SL_ / 2)     // 12 packed f32x2 pairs

// Main-kernel tiling
#define TPB_ 256           // threads per block
#define QPT_ 4             // q positions per thread
#define QPB_ (TPB_ * QPT_) // 1024 q per block
#define BLKS_PER_B_ (QL_ / QPB_) // 16

// Scratch: projected context sourceT[b][i][l] (384 KB) + mask bias (3 KB)
__device__ float g_sourceT[B_ * IDF_ * SL_];
__device__ float g_sbias[B_ * SL_];

// ---- packed f32x2 helpers (sm_103a; ptxas never auto-fuses these) ----
__device__ __forceinline__ unsigned long long pack2(float a, float b) {
    unsigned long long r;
    asm("mov.b64 %0, {%1, %2};" : "=l"(r) : "f"(a), "f"(b));
    return r;
}
__device__ __forceinline__ void unpack2(unsigned long long v, float& a, float& b) {
    asm("mov.b64 {%0, %1}, %2;" : "=f"(a), "=f"(b) : "l"(v));
}
__device__ __forceinline__ unsigned long long ffma2(unsigned long long a,
                                                    unsigned long long b,
                                                    unsigned long long c) {
    unsigned long long d;
    asm("fma.rn.f32x2 %0, %1, %2, %3;" : "=l"(d) : "l"(a), "l"(b), "l"(c));
    return d;
}
__device__ __forceinline__ void stcs(float* p, float v) {
    asm volatile("st.global.cs.f32 [%0], %1;" :: "l"(p), "f"(v) : "memory");
}

// ---------------------------------------------------------------------------
// Kernel 0: classify mask encoding (uint8 / int32 / float32) from its byte
// pattern and materialize g_sbias[b*SL+l] = masked ? -inf : 0.
// Reads only the first B*SL bytes for classification (in-bounds for every
// candidate dtype); wider reads happen only once the dtype is proven.
// ---------------------------------------------------------------------------
__global__ void mask_kernel(const unsigned char* __restrict__ m8)
{
    __shared__ int s_off, s_badf;
    const int tid = threadIdx.x;
    if (tid == 0) { s_off = 0; s_badf = 0; }
    __syncthreads();

    int n_off = 0, bad_f = 0;
    for (int i = tid; i < B_ * SL_; i += blockDim.x) {
        const unsigned char v = m8[i];
        const int r = i & 3;
        if (r != 0 && v != 0) n_off++;
        // fp32 pattern for {0.0f, 1.0f}: bytes [0, 0, 0x80|0, 0x3F|0]
        if (r == 0 && v != 0) bad_f++;
        if (r == 1 && v != 0) bad_f++;
        if (r == 2 && v != 0 && v != 0x80) bad_f++;
        if (r == 3 && v != 0 && v != 0x3F) bad_f++;
    }
    atomicAdd(&s_off, n_off);
    atomicAdd(&s_badf, bad_f);
    __syncthreads();

    int cls;                       // 0 = uint8, 1 = int32, 2 = float32
    if (s_off == 0)       cls = 1; // only word-LSB bytes set -> int32 {0,1}
    else if (s_badf == 0) cls = 2; // matches fp32 {0,1} pattern -> float32
    else                  cls = 0; // genuine byte bools

    for (int i = tid; i < B_ * SL_; i += blockDim.x) {
        bool mv;
        if (cls == 1)      mv = (reinterpret_cast<const int*>(m8)[i] != 0);
        else if (cls == 2) mv = (reinterpret_cast<const float*>(m8)[i] != 0.0f);
        else               mv = (m8[i] != 0);
        g_sbias[i] = mv ? -INFINITY : 0.0f;
    }
}

// ---------------------------------------------------------------------------
// Kernel 1: sourceT[b,i,l] = sum_c W[i,c] * context[b,c,l]
// ---------------------------------------------------------------------------
__global__ __launch_bounds__(IDF_)
void proj_kernel(const float* __restrict__ context, const float* __restrict__ W)
{
    __shared__ float sctx[CDF_ * SL_];   // 24 KB
    const int b = blockIdx.x;

    const float* ctx = context + (size_t)b * CDF_ * SL_;
    for (int idx = threadIdx.x; idx < CDF_ * SL_; idx += blockDim.x)
        sctx[idx] = ctx[idx];
    __syncthreads();

    const int i = threadIdx.x;           // 0..127
    float acc[SL_];
#pragma unroll
    for (int l = 0; l < SL_; l++) acc[l] = 0.0f;

    const float* wrow = W + (size_t)i * CDF_;
#pragma unroll 4
    for (int c = 0; c < CDF_; c++) {
        const float w = wrow[c];
        const float* sc = sctx + c * SL_;
#pragma unroll
        for (int l = 0; l < SL_; l++)
            acc[l] = fmaf(w, sc[l], acc[l]);
    }

    float* dst = g_sourceT + ((size_t)b * IDF_ + i) * SL_;
#pragma unroll
    for (int l = 0; l < SL_; l++) dst[l] = acc[l];
}

// ---------------------------------------------------------------------------
// Kernel 2: fused attention with packed f32x2 math + SW-pipelined input loads.
// ---------------------------------------------------------------------------
__global__ __launch_bounds__(TPB_)
void attn_kernel(const float* __restrict__ input,
                 float* __restrict__ wc,
                 float* __restrict__ attn_out)
{
    __shared__ float ss[IDF_ * SL_];     // 12 KB
    __shared__ float sbias[SL_];

    const int b     = blockIdx.x >> 4;                // / BLKS_PER_B_
    const int qblk  = blockIdx.x & (BLKS_PER_B_ - 1);
    const int qbase = qblk * QPB_;
    const int tid   = threadIdx.x;

    // Stage sourceT[b] and mask bias
    {
        const float* sp = g_sourceT + (size_t)b * IDF_ * SL_;
        for (int idx = tid; idx < IDF_ * SL_; idx += TPB_)
            ss[idx] = sp[idx];
        if (tid < SL_)
            sbias[tid] = g_sbias[b * SL_ + tid];
    }
    __syncthreads();

    // ---- Phase 1: logits (packed accumulators: 12 f32x2 pairs per q) ----
    unsigned long long accp[QPT_][SLP_];
#pragma unroll
    for (int k = 0; k < QPT_; k++)
#pragma unroll
        for (int j = 0; j < SLP_; j++) accp[k][j] = 0ull;

    const float* tbase = input + (size_t)b * IDF_ * QL_ + qbase + tid;

    // Software pipeline: prefetch iteration i+1 while consuming i.
    float tcur[QPT_], tnxt[QPT_];
#pragma unroll
    for (int k = 0; k < QPT_; k++)
        tcur[k] = __ldg(tbase + k * TPB_);

#pragma unroll 2
    for (int i = 0; i < IDF_; i++) {
        if (i + 1 < IDF_) {
#pragma unroll
            for (int k = 0; k < QPT_; k++)
                tnxt[k] = __ldg(tbase + (size_t)(i + 1) * QL_ + k * TPB_);
        }

        unsigned long long tp[QPT_];
#pragma unroll
        for (int k = 0; k < QPT_; k++)
            tp[k] = pack2(tcur[k], tcur[k]);

        const ulonglong2* s2 = reinterpret_cast<const ulonglong2*>(ss + i * SL_);
#pragma unroll
        for (int j = 0; j < SLP_ / 2; j++) {       // 6 x 16B smem loads
            const ulonglong2 v = s2[j];
#pragma unroll
            for (int k = 0; k < QPT_; k++) {
                accp[k][2*j + 0] = ffma2(tp[k], v.x, accp[k][2*j + 0]);
                accp[k][2*j + 1] = ffma2(tp[k], v.y, accp[k][2*j + 1]);
            }
        }

#pragma unroll
        for (int k = 0; k < QPT_; k++)
            tcur[k] = tnxt[k];
    }

    // ---- Softmax over l, write attn_out (streaming), repack weights ----
    float* abase = attn_out + (size_t)b * SL_ * QL_ + qbase + tid;
#pragma unroll
    for (int k = 0; k < QPT_; k++) {
        float p[SL_];
#pragma unroll
        for (int j = 0; j < SLP_; j++)
            unpack2(accp[k][j], p[2*j], p[2*j + 1]);

        float m = -INFINITY;
#pragma unroll
        for (int l = 0; l < SL_; l++) {
            p[l] += sbias[l];
            m = fmaxf(m, p[l]);
        }
        float sum = 0.0f;
#pragma unroll
        for (int l = 0; l < SL_; l++) {
            const float e = __expf(p[l] - m);
            p[l] = e;
            sum += e;
        }
        const float inv = 1.0f / sum;
#pragma unroll
        for (int l = 0; l < SL_; l++) {
            p[l] *= inv;
            stcs(abase + (size_t)l * QL_ + k * TPB_, p[l]);
        }
#pragma unroll
        for (int j = 0; j < SLP_; j++)
            accp[k][j] = pack2(p[2*j], p[2*j + 1]);   // reuse as packed weights
    }

    // ---- Phase 2: weighted context (packed dot over l, streaming stores) ----
    float* wbase = wc + (size_t)b * IDF_ * QL_ + qbase + tid;

#pragma unroll 2
    for (int i = 0; i < IDF_; i++) {
        const ulonglong2* s2 = reinterpret_cast<const ulonglong2*>(ss + i * SL_);
        unsigned long long wp[QPT_];
#pragma unroll
        for (int k = 0; k < QPT_; k++) wp[k] = 0ull;
#pragma unroll
        for (int j = 0; j < SLP_ / 2; j++) {
            const ulonglong2 v = s2[j];
#pragma unroll
            for (int k = 0; k < QPT_; k++) {
                wp[k] = ffma2(v.x, accp[k][2*j + 0], wp[k]);
                wp[k] = ffma2(v.y, accp[k][2*j + 1], wp[k]);
            }
        }
#pragma unroll
        for (int k = 0; k < QPT_; k++) {
            float lo, hi;
            unpack2(wp[k], lo, hi);
            stcs(wbase + (size_t)i * QL_ + k * TPB_, lo + hi);
        }
    }
}

// ---------------------------------------------------------------------------
// Harness entry point
// Inputs (metadata order): input f32 (32,128,128,128), context f32 (32,256,24),
//                          W f32 (128,256), mask (32,24) in unknown encoding.
// Output: weightedContext f32 (32,128,128,128) followed by
//         attn f32 (32,24,128,128), concatenated in d_out.
// ---------------------------------------------------------------------------
extern "C" void kernel_launch(void* const* d_in, const int* in_sizes, int n_in,
                              void* d_out, int out_size)
{
    const float*         input   = (const float*)d_in[0];
    const float*         context = (const float*)d_in[1];
    const float*         W       = (const float*)d_in[2];
    const unsigned char* mask    = (const unsigned char*)d_in[3];

    float* out  = (float*)d_out;
    float* wc   = out;                                  // 32*128*16384
    float* attn = out + (size_t)B_ * IDF_ * QL_;        // 32*24*16384

    mask_kernel<<<1, 256>>>(mask);
    proj_kernel<<<B_, IDF_>>>(context, W);
    attn_kernel<<<B_ * BLKS_PER_B_, TPB_>>>(input, wc, attn);
}

// round 5
// speedup vs baseline: 1.3951x; 1.3951x over previous
#include <cuda_runtime.h>
#include <cuda_bf16.h>
#include <math.h>

// Problem constants (from reference setup_inputs)
#define B_   32
#define IDF_ 128
#define CDF_ 256
#define IH_  128
#define IW_  128
#define QL_  (IH_ * IW_)   // 16384
#define SL_  24
#define SLP_ (SL_ / 2)     // 12 packed f32x2 pairs

// attn tiling: 128 threads, 4 CONSECUTIVE q per thread (float4 I/O)
#define TPB_ 128
#define QPT_ 4
#define QPB_ (TPB_ * QPT_)        // 512 q per block
#define BLKS_PER_B_ (QL_ / QPB_)  // 32

// Scratch: projected context sourceT[b][i][l] (384 KB) + mask bias (3 KB)
__device__ float g_sourceT[B_ * IDF_ * SL_];
__device__ float g_sbias[B_ * SL_];

// ---- packed f32x2 helpers (sm_103a; ptxas never auto-fuses these) ----
__device__ __forceinline__ unsigned long long pack2(float a, float b) {
    unsigned long long r;
    asm("mov.b64 %0, {%1, %2};" : "=l"(r) : "f"(a), "f"(b));
    return r;
}
__device__ __forceinline__ void unpack2(unsigned long long v, float& a, float& b) {
    asm("mov.b64 {%0, %1}, %2;" : "=f"(a), "=f"(b) : "l"(v));
}
__device__ __forceinline__ unsigned long long ffma2(unsigned long long a,
                                                    unsigned long long b,
                                                    unsigned long long c) {
    unsigned long long d;
    asm("fma.rn.f32x2 %0, %1, %2, %3;" : "=l"(d) : "l"(a), "l"(b), "l"(c));
    return d;
}
__device__ __forceinline__ void stcs4(float4* p, float4 v) {
    asm volatile("st.global.cs.v4.f32 [%0], {%1, %2, %3, %4};"
                 :: "l"(p), "f"(v.x), "f"(v.y), "f"(v.z), "f"(v.w) : "memory");
}

// ---------------------------------------------------------------------------
// Kernel 1: mask classification + bias materialization + projection.
//   g_sbias[b,l]   = masked ? -inf : 0   (mask dtype sniffed from bytes)
//   sourceT[b,i,l] = sum_c W[i,c] * context[b,c,l]
// One block per batch, 128 threads (one per i).
// ---------------------------------------------------------------------------
__global__ __launch_bounds__(IDF_)
void proj_kernel(const float* __restrict__ context, const float* __restrict__ W,
                 const unsigned char* __restrict__ m8)
{
    __shared__ float sctx[CDF_ * SL_];   // 24 KB
    __shared__ int s_off, s_badf;
    const int b   = blockIdx.x;
    const int tid = threadIdx.x;

    if (tid == 0) { s_off = 0; s_badf = 0; }
    __syncthreads();

    // --- mask byte-pattern classification over first B*SL bytes (in-bounds
    //     for every candidate dtype: uint8 / int32 / float32) ---
    {
        int n_off = 0, bad_f = 0;
        for (int i = tid; i < B_ * SL_; i += blockDim.x) {
            const unsigned char v = m8[i];
            const int r = i & 3;
            if (r != 0 && v != 0) n_off++;
            if (r == 0 && v != 0) bad_f++;
            if (r == 1 && v != 0) bad_f++;
            if (r == 2 && v != 0 && v != 0x80) bad_f++;
            if (r == 3 && v != 0 && v != 0x3F) bad_f++;
        }
        if (n_off) atomicAdd(&s_off, n_off);
        if (bad_f) atomicAdd(&s_badf, bad_f);
    }

    // --- stage context tile while the atomics settle ---
    const float* ctx = context + (size_t)b * CDF_ * SL_;
    for (int idx = tid; idx < CDF_ * SL_; idx += blockDim.x)
        sctx[idx] = ctx[idx];
    __syncthreads();

    // --- write this batch's bias row ---
    if (tid < SL_) {
        const int cls = (s_off == 0) ? 1 : (s_badf == 0 ? 2 : 0);
        const int i = b * SL_ + tid;
        bool mv;
        if (cls == 1)      mv = (reinterpret_cast<const int*>(m8)[i] != 0);
        else if (cls == 2) mv = (reinterpret_cast<const float*>(m8)[i] != 0.0f);
        else               mv = (m8[i] != 0);
        g_sbias[i] = mv ? -INFINITY : 0.0f;
    }

    // --- projection ---
    const int i = tid;                   // 0..127
    float acc[SL_];
#pragma unroll
    for (int l = 0; l < SL_; l++) acc[l] = 0.0f;

    const float* wrow = W + (size_t)i * CDF_;
#pragma unroll 4
    for (int c = 0; c < CDF_; c++) {
        const float w = wrow[c];
        const float* sc = sctx + c * SL_;
#pragma unroll
        for (int l = 0; l < SL_; l++)
            acc[l] = fmaf(w, sc[l], acc[l]);
    }

    float* dst = g_sourceT + ((size_t)b * IDF_ + i) * SL_;
#pragma unroll
    for (int l = 0; l < SL_; l++) dst[l] = acc[l];
}

// ---------------------------------------------------------------------------
// Kernel 2: fused attention. Packed f32x2 math, float4 I/O, SW pipeline.
// Each thread owns 4 CONSECUTIVE q (LDG.128 / STG.128, fully coalesced).
// ---------------------------------------------------------------------------
__global__ __launch_bounds__(TPB_, 3)
void attn_kernel(const float* __restrict__ input,
                 float* __restrict__ wc,
                 float* __restrict__ attn_out)
{
    __shared__ float ss[IDF_ * SL_];     // 12 KB
    __shared__ float sbias[SL_];

    const int b     = blockIdx.x >> 5;                // / BLKS_PER_B_
    const int qblk  = blockIdx.x & (BLKS_PER_B_ - 1);
    const int qbase = qblk * QPB_;
    const int tid   = threadIdx.x;

    // Stage sourceT[b] (float4 loads) and mask bias
    {
        const float4* sp4 = reinterpret_cast<const float4*>(g_sourceT + (size_t)b * IDF_ * SL_);
        float4* ss4 = reinterpret_cast<float4*>(ss);
#pragma unroll
        for (int idx = tid; idx < IDF_ * SL_ / 4; idx += TPB_)
            ss4[idx] = sp4[idx];
        if (tid < SL_)
            sbias[tid] = g_sbias[b * SL_ + tid];
    }
    __syncthreads();

    // ---- Phase 1: logits (packed accumulators: 12 f32x2 pairs per q) ----
    unsigned long long accp[QPT_][SLP_];
#pragma unroll
    for (int k = 0; k < QPT_; k++)
#pragma unroll
        for (int j = 0; j < SLP_; j++) accp[k][j] = 0ull;

    const float4* tbase4 =
        reinterpret_cast<const float4*>(input + (size_t)b * IDF_ * QL_ + qbase) + tid;

    // Software pipeline: prefetch iteration i+1 while consuming i.
    float4 tcur = tbase4[0], tnxt;

#pragma unroll 2
    for (int i = 0; i < IDF_; i++) {
        if (i + 1 < IDF_)
            tnxt = tbase4[(size_t)(i + 1) * (QL_ / 4)];

        unsigned long long tp[QPT_];
        tp[0] = pack2(tcur.x, tcur.x);
        tp[1] = pack2(tcur.y, tcur.y);
        tp[2] = pack2(tcur.z, tcur.z);
        tp[3] = pack2(tcur.w, tcur.w);

        const ulonglong2* s2 = reinterpret_cast<const ulonglong2*>(ss + i * SL_);
#pragma unroll
        for (int j = 0; j < SLP_ / 2; j++) {       // 6 x LDS.128 (broadcast)
            const ulonglong2 v = s2[j];
#pragma unroll
            for (int k = 0; k < QPT_; k++) {
                accp[k][2*j + 0] = ffma2(tp[k], v.x, accp[k][2*j + 0]);
                accp[k][2*j + 1] = ffma2(tp[k], v.y, accp[k][2*j + 1]);
            }
        }
        tcur = tnxt;
    }

    // ---- Softmax over l for all 4 q, then 24 x STG.128 to attn_out ----
    float p[QPT_][SL_];
#pragma unroll
    for (int k = 0; k < QPT_; k++) {
#pragma unroll
        for (int j = 0; j < SLP_; j++)
            unpack2(accp[k][j], p[k][2*j], p[k][2*j + 1]);

        float m = -INFINITY;
#pragma unroll
        for (int l = 0; l < SL_; l++) {
            p[k][l] += sbias[l];
            m = fmaxf(m, p[k][l]);
        }
        float sum = 0.0f;
#pragma unroll
        for (int l = 0; l < SL_; l++) {
            const float e = __expf(p[k][l] - m);
            p[k][l] = e;
            sum += e;
        }
        const float inv = 1.0f / sum;
#pragma unroll
        for (int l = 0; l < SL_; l++)
            p[k][l] *= inv;
    }

    {
        float4* abase4 =
            reinterpret_cast<float4*>(attn_out + (size_t)b * SL_ * QL_ + qbase) + tid;
#pragma unroll
        for (int l = 0; l < SL_; l++)
            stcs4(abase4 + (size_t)l * (QL_ / 4),
                  make_float4(p[0][l], p[1][l], p[2][l], p[3][l]));
    }

    // Repack weights for phase 2
#pragma unroll
    for (int k = 0; k < QPT_; k++)
#pragma unroll
        for (int j = 0; j < SLP_; j++)
            accp[k][j] = pack2(p[k][2*j], p[k][2*j + 1]);

    // ---- Phase 2: weighted context (packed dot over l, STG.128) ----
    float4* wbase4 =
        reinterpret_cast<float4*>(wc + (size_t)b * IDF_ * QL_ + qbase) + tid;

#pragma unroll 2
    for (int i = 0; i < IDF_; i++) {
        const ulonglong2* s2 = reinterpret_cast<const ulonglong2*>(ss + i * SL_);
        unsigned long long wp[QPT_];
#pragma unroll
        for (int k = 0; k < QPT_; k++) wp[k] = 0ull;
#pragma unroll
        for (int j = 0; j < SLP_ / 2; j++) {
            const ulonglong2 v = s2[j];
#pragma unroll
            for (int k = 0; k < QPT_; k++) {
                wp[k] = ffma2(v.x, accp[k][2*j + 0], wp[k]);
                wp[k] = ffma2(v.y, accp[k][2*j + 1], wp[k]);
            }
        }
        float w[QPT_];
#pragma unroll
        for (int k = 0; k < QPT_; k++) {
            float lo, hi;
            unpack2(wp[k], lo, hi);
            w[k] = lo + hi;
        }
        stcs4(wbase4 + (size_t)i * (QL_ / 4), make_float4(w[0], w[1], w[2], w[3]));
    }
}

// ---------------------------------------------------------------------------
// Harness entry point
// Inputs (metadata order): input f32 (32,128,128,128), context f32 (32,256,24),
//                          W f32 (128,256), mask (32,24) in sniffed encoding.
// Output: weightedContext f32 (32,128,128,128) followed by
//         attn f32 (32,24,128,128), concatenated in d_out.
// ---------------------------------------------------------------------------
extern "C" void kernel_launch(void* const* d_in, const int* in_sizes, int n_in,
                              void* d_out, int out_size)
{
    const float*         input   = (const float*)d_in[0];
    const float*         context = (const float*)d_in[1];
    const float*         W       = (const float*)d_in[2];
    const unsigned char* mask    = (const unsigned char*)d_in[3];

    float* out  = (float*)d_out;
    float* wc   = out;                                  // 32*128*16384
    float* attn = out + (size_t)B_ * IDF_ * QL_;        // 32*24*16384

    proj_kernel<<<B_, IDF_>>>(context, W, mask);
    attn_kernel<<<B_ * BLKS_PER_B_, TPB_>>>(input, wc, attn);
}